// round 6
// baseline (speedup 1.0000x reference)
#include <cuda_runtime.h>
#include <cuda_bf16.h>
#include <cstdint>

// Problem constants
#define BB 2
#define SS 2048
#define DD 1024
#define HH 16
#define HS 64
#define INV_SCALE 0.125f
#define KP3 3072   // packed K = [hi | lo | hi] (A) / [hi | hi | lo] (B)

// Q,K: [bh][s][hs] bf16 hi/lo.  V: TRANSPOSED [bh][hs][s] bf16 hi/lo.
__device__ __nv_bfloat16 g_Qh[BB * HH * SS * HS];
__device__ __nv_bfloat16 g_Ql[BB * HH * SS * HS];
__device__ __nv_bfloat16 g_Kh[BB * HH * SS * HS];
__device__ __nv_bfloat16 g_Kl[BB * HH * SS * HS];
__device__ __nv_bfloat16 g_Vh[BB * HH * SS * HS];
__device__ __nv_bfloat16 g_Vl[BB * HH * SS * HS];

// Prepacked GEMM operands
__device__ __nv_bfloat16 g_xp[(size_t)BB * SS * KP3];        // [4096][3072]
__device__ __nv_bfloat16 g_wp[(size_t)3 * DD * KP3];         // [3][1024][3072]

#define MMA_BF16(c, a, b) asm volatile( \
    "mma.sync.aligned.m16n8k16.row.col.f32.bf16.bf16.f32 " \
    "{%0,%1,%2,%3}, {%4,%5,%6,%7}, {%8,%9}, {%0,%1,%2,%3};\n" \
    : "+f"((c)[0]), "+f"((c)[1]), "+f"((c)[2]), "+f"((c)[3]) \
    : "r"((a)[0]), "r"((a)[1]), "r"((a)[2]), "r"((a)[3]), \
      "r"((b)[0]), "r"((b)[1]))

#define LDSM4(r0, r1, r2, r3, addr) asm volatile( \
    "ldmatrix.sync.aligned.m8n8.x4.shared.b16 {%0,%1,%2,%3}, [%4];\n" \
    : "=r"(r0), "=r"(r1), "=r"(r2), "=r"(r3) : "r"(addr))

#define CP_ASYNC16(dst, src) asm volatile( \
    "cp.async.cg.shared.global [%0], [%1], 16;\n" :: "r"(dst), "l"(src))
#define CP_COMMIT() asm volatile("cp.async.commit_group;\n")
#define CP_WAIT1()  asm volatile("cp.async.wait_group 1;\n")

__device__ __forceinline__ uint32_t pack_bf16x2(float lo_elem, float hi_elem) {
    __nv_bfloat162 h = __floats2bfloat162_rn(lo_elem, hi_elem); // .x = low 16 bits
    uint32_t u;
    memcpy(&u, &h, 4);
    return u;
}

// ---------------------------------------------------------------------------
// Pre-pass: split fp32 into bf16 hi/lo, pack K-extended operands.
// A: [hi | lo | hi]   B: [hi | hi | lo]
// ---------------------------------------------------------------------------
__global__ __launch_bounds__(256) void prep_x_kernel(const float* __restrict__ x)
{
    const size_t i = ((size_t)blockIdx.x * 256 + threadIdx.x) * 4;  // over 4M elems
    const int m = (int)(i >> 10);
    const int k = (int)(i & 1023);
    float4 v = *(const float4*)(x + i);
    float f[4] = {v.x, v.y, v.z, v.w};
    uint32_t hw[2], lw[2];
    #pragma unroll
    for (int p = 0; p < 2; p++) {
        float h0 = __bfloat162float(__float2bfloat16_rn(f[2 * p]));
        float h1 = __bfloat162float(__float2bfloat16_rn(f[2 * p + 1]));
        hw[p] = pack_bf16x2(h0, h1);
        lw[p] = pack_bf16x2(f[2 * p] - h0, f[2 * p + 1] - h1);
    }
    __nv_bfloat16* row = g_xp + (size_t)m * KP3;
    *(uint2*)(row + k)        = make_uint2(hw[0], hw[1]);
    *(uint2*)(row + 1024 + k) = make_uint2(lw[0], lw[1]);
    *(uint2*)(row + 2048 + k) = make_uint2(hw[0], hw[1]);
}

__global__ __launch_bounds__(256) void prep_w_kernel(
    const float* __restrict__ Wq, const float* __restrict__ Wk,
    const float* __restrict__ Wv)
{
    const int z = blockIdx.z;
    const float* W = (z == 0) ? Wq : (z == 1) ? Wk : Wv;
    const size_t i = ((size_t)blockIdx.x * 256 + threadIdx.x) * 4;  // over 1M elems
    const int n = (int)(i >> 10);
    const int k = (int)(i & 1023);
    float4 v = *(const float4*)(W + i);
    float f[4] = {v.x, v.y, v.z, v.w};
    uint32_t hw[2], lw[2];
    #pragma unroll
    for (int p = 0; p < 2; p++) {
        float h0 = __bfloat162float(__float2bfloat16_rn(f[2 * p]));
        float h1 = __bfloat162float(__float2bfloat16_rn(f[2 * p + 1]));
        hw[p] = pack_bf16x2(h0, h1);
        lw[p] = pack_bf16x2(f[2 * p] - h0, f[2 * p + 1] - h1);
    }
    __nv_bfloat16* row = g_wp + ((size_t)z * DD + n) * KP3;
    *(uint2*)(row + k)        = make_uint2(hw[0], hw[1]);
    *(uint2*)(row + 1024 + k) = make_uint2(hw[0], hw[1]);
    *(uint2*)(row + 2048 + k) = make_uint2(lw[0], lw[1]);
}

// ---------------------------------------------------------------------------
// QKV GEMM: plain bf16 GEMM over packed K=3072 (compensation baked in).
// Block 128x128, BK=32, 256 thr = 8 warps (2m x 4n), warp 64x32.
// cp.async double-buffer, ldmatrix fragment loads, stride-20 padded smem.
// ---------------------------------------------------------------------------
#define GBM 128
#define GBN 128
#define GBK 32
#define GSTR 20                 // u32 per smem row (16 data + 4 pad)
#define STAGE_BYTES (128 * GSTR * 4)
#define NKT (KP3 / GBK)         // 96

__global__ __launch_bounds__(256) void qkv_gemm_kernel(
    const float* __restrict__ bq, const float* __restrict__ bk,
    const float* __restrict__ bv)
{
    const int z = blockIdx.z;
    const float* bias = (z == 0) ? bq : (z == 1) ? bk : bv;
    __nv_bfloat16* __restrict__ outh = (z == 0) ? g_Qh : (z == 1) ? g_Kh : g_Vh;
    __nv_bfloat16* __restrict__ outl = (z == 0) ? g_Ql : (z == 1) ? g_Kl : g_Vl;
    const bool vtrans = (z == 2);

    const __nv_bfloat16* __restrict__ xp = g_xp;
    const __nv_bfloat16* __restrict__ wp = g_wp + (size_t)z * DD * KP3;

    __shared__ __align__(16) uint32_t sA[2][128 * GSTR];
    __shared__ __align__(16) uint32_t sB[2][128 * GSTR];

    const int m0 = blockIdx.y * GBM;
    const int n0 = blockIdx.x * GBN;
    const int t    = threadIdx.x;
    const int wid  = t >> 5;
    const int lane = t & 31;
    const int wm = (wid & 1) * 64;
    const int wn = (wid >> 1) * 32;
    const int g  = lane >> 2;
    const int tq = lane & 3;

    const uint32_t sA0 = (uint32_t)__cvta_generic_to_shared(&sA[0][0]);
    const uint32_t sB0 = (uint32_t)__cvta_generic_to_shared(&sB[0][0]);

    // cp.async mapping: row = t&127, half = t>>7 (16 bf16), 2x16B chunks
    const int crow  = t & 127;
    const int chalf = t >> 7;
    const __nv_bfloat16* asrc_base = xp + (size_t)(m0 + crow) * KP3 + chalf * 16;
    const __nv_bfloat16* bsrc_base = wp + (size_t)(n0 + crow) * KP3 + chalf * 16;
    const uint32_t adst_base = sA0 + (crow * GSTR + chalf * 8) * 4;
    const uint32_t bdst_base = sB0 + (crow * GSTR + chalf * 8) * 4;

    // ldmatrix per-lane offset: row = lane&15, k-quad = lane>>4 (16B)
    const uint32_t lmoff = (uint32_t)((lane & 15) * (GSTR * 4) + (lane >> 4) * 16);

    float acc[4][4][4];
    #pragma unroll
    for (int mi = 0; mi < 4; mi++)
        #pragma unroll
        for (int ni = 0; ni < 4; ni++)
            #pragma unroll
            for (int c = 0; c < 4; c++) acc[mi][ni][c] = 0.0f;

    // Prologue: fill both stages
    #pragma unroll
    for (int pre = 0; pre < 2; pre++) {
        const int koff = pre * GBK;
        const uint32_t so = pre * STAGE_BYTES;
        CP_ASYNC16(adst_base + so,      asrc_base + koff);
        CP_ASYNC16(adst_base + so + 16, asrc_base + koff + 8);
        CP_ASYNC16(bdst_base + so,      bsrc_base + koff);
        CP_ASYNC16(bdst_base + so + 16, bsrc_base + koff + 8);
        CP_COMMIT();
    }

    for (int kt = 0; kt < NKT; kt++) {
        const int s = kt & 1;
        const uint32_t so = s * STAGE_BYTES;
        CP_WAIT1();
        __syncthreads();

        // Load all fragments for this stage into registers
        uint32_t a[2][4][4], b[2][4][2];
        #pragma unroll
        for (int kk = 0; kk < 2; kk++) {
            #pragma unroll
            for (int mi = 0; mi < 4; mi++) {
                const uint32_t addr = sA0 + so +
                    (uint32_t)((wm + mi * 16) * (GSTR * 4) + kk * 32) + lmoff;
                LDSM4(a[kk][mi][0], a[kk][mi][1], a[kk][mi][2], a[kk][mi][3], addr);
            }
            #pragma unroll
            for (int np = 0; np < 2; np++) {
                const uint32_t addr = sB0 + so +
                    (uint32_t)((wn + np * 16) * (GSTR * 4) + kk * 32) + lmoff;
                uint32_t r0, r1, r2, r3;
                LDSM4(r0, r1, r2, r3, addr);
                b[kk][2 * np][0]     = r0;  b[kk][2 * np][1]     = r2;
                b[kk][2 * np + 1][0] = r1;  b[kk][2 * np + 1][1] = r3;
            }
        }
        __syncthreads();   // all warps done reading stage s

        // Refill stage s for kt+2 (overlaps with MMA burst)
        if (kt + 2 < NKT) {
            const int koff = (kt + 2) * GBK;
            CP_ASYNC16(adst_base + so,      asrc_base + koff);
            CP_ASYNC16(adst_base + so + 16, asrc_base + koff + 8);
            CP_ASYNC16(bdst_base + so,      bsrc_base + koff);
            CP_ASYNC16(bdst_base + so + 16, bsrc_base + koff + 8);
        }
        CP_COMMIT();

        #pragma unroll
        for (int kk = 0; kk < 2; kk++)
            #pragma unroll
            for (int mi = 0; mi < 4; mi++)
                #pragma unroll
                for (int ni = 0; ni < 4; ni++)
                    MMA_BF16(acc[mi][ni], a[kk][mi], b[kk][ni]);
    }

    // Epilogue: bias, hi/lo split, scatter. Q/K: [bh][s][hs]; V: [bh][hs][s].
    #pragma unroll
    for (int mi = 0; mi < 4; mi++) {
        #pragma unroll
        for (int ni = 0; ni < 4; ni++) {
            const int r0 = m0 + wm + mi * 16 + g;
            const int c0 = n0 + wn + ni * 8 + 2 * tq;
            #pragma unroll
            for (int c = 0; c < 4; c++) {
                const int row = r0 + (c >> 1) * 8;
                const int col = c0 + (c & 1);
                const int b_  = row >> 11;
                const int s_  = row & (SS - 1);
                const int h_  = col >> 6;
                const int hs_ = col & (HS - 1);
                const float v = acc[mi][ni][c] + __ldg(&bias[col]);
                __nv_bfloat16 vh = __float2bfloat16_rn(v);
                __nv_bfloat16 vl = __float2bfloat16_rn(v - __bfloat162float(vh));
                size_t idx;
                if (!vtrans) idx = ((size_t)(b_ * HH + h_) * SS + s_) * HS + hs_;
                else         idx = ((size_t)(b_ * HH + h_) * HS + hs_) * SS + s_;
                outh[idx] = vh;
                outl[idx] = vl;
            }
        }
    }
}

// ---------------------------------------------------------------------------
// Flash attention on tensor cores (bf16x3 compensated), causal.
// Unchanged from passing R4 kernel.
// ---------------------------------------------------------------------------
#define QT 64
#define KT 64
#define ASTR 36

__global__ __launch_bounds__(128) void attn_mma_kernel(float* __restrict__ out)
{
    const int bh = blockIdx.y;
    const int jq = (SS / QT - 1) - blockIdx.x;   // heavy tiles first
    const int b  = bh >> 4;
    const int h  = bh & (HH - 1);

    __shared__ uint32_t sK[2][64 * ASTR];  // [hi/lo][key][d-words]
    __shared__ uint32_t sV[2][64 * ASTR];  // [hi/lo][d][key-words]

    const int t    = threadIdx.x;
    const int wid  = t >> 5;
    const int lane = t & 31;
    const int g  = lane >> 2;
    const int tq = lane & 3;
    const int q0 = jq * QT + wid * 16;

    const uint32_t* Qh32 = (const uint32_t*)g_Qh + (size_t)bh * SS * (HS / 2);
    const uint32_t* Ql32 = (const uint32_t*)g_Ql + (size_t)bh * SS * (HS / 2);
    const uint32_t* Kh32 = (const uint32_t*)g_Kh + (size_t)bh * SS * (HS / 2);
    const uint32_t* Kl32 = (const uint32_t*)g_Kl + (size_t)bh * SS * (HS / 2);
    const uint32_t* Vh32 = (const uint32_t*)g_Vh + (size_t)bh * HS * (SS / 2);
    const uint32_t* Vl32 = (const uint32_t*)g_Vl + (size_t)bh * HS * (SS / 2);

    uint32_t qh[4][4], ql[4][4];
    #pragma unroll
    for (int kt = 0; kt < 4; kt++) {
        const int w = 8 * kt + tq;
        qh[kt][0] = Qh32[(size_t)(q0 + g) * 32 + w];
        qh[kt][1] = Qh32[(size_t)(q0 + g + 8) * 32 + w];
        qh[kt][2] = Qh32[(size_t)(q0 + g) * 32 + w + 4];
        qh[kt][3] = Qh32[(size_t)(q0 + g + 8) * 32 + w + 4];
        ql[kt][0] = Ql32[(size_t)(q0 + g) * 32 + w];
        ql[kt][1] = Ql32[(size_t)(q0 + g + 8) * 32 + w];
        ql[kt][2] = Ql32[(size_t)(q0 + g) * 32 + w + 4];
        ql[kt][3] = Ql32[(size_t)(q0 + g + 8) * 32 + w + 4];
    }

    float oacc[8][4];
    #pragma unroll
    for (int j = 0; j < 8; j++)
        #pragma unroll
        for (int c = 0; c < 4; c++) oacc[j][c] = 0.0f;
    float mrow[2] = {-1e30f, -1e30f};
    float lrow[2] = {0.0f, 0.0f};

    const int cr = t >> 1;
    const int cs = (t & 1) * 16;

    for (int jt = 0; jt <= jq; jt++) {
        const int k0 = jt * KT;
        __syncthreads();
        {
            const uint4* skh = (const uint4*)(Kh32 + (size_t)(k0 + cr) * 32 + cs);
            const uint4* skl = (const uint4*)(Kl32 + (size_t)(k0 + cr) * 32 + cs);
            const uint4* svh = (const uint4*)(Vh32 + (size_t)cr * (SS / 2) + k0 / 2 + cs);
            const uint4* svl = (const uint4*)(Vl32 + (size_t)cr * (SS / 2) + k0 / 2 + cs);
            uint4* dkh = (uint4*)&sK[0][cr * ASTR + cs];
            uint4* dkl = (uint4*)&sK[1][cr * ASTR + cs];
            uint4* dvh = (uint4*)&sV[0][cr * ASTR + cs];
            uint4* dvl = (uint4*)&sV[1][cr * ASTR + cs];
            #pragma unroll
            for (int u = 0; u < 4; u++) {
                dkh[u] = skh[u];
                dkl[u] = skl[u];
                dvh[u] = svh[u];
                dvl[u] = svl[u];
            }
        }
        __syncthreads();

        float s[8][4];
        #pragma unroll
        for (int j = 0; j < 8; j++)
            #pragma unroll
            for (int c = 0; c < 4; c++) s[j][c] = 0.0f;
        #pragma unroll
        for (int j = 0; j < 8; j++) {
            #pragma unroll
            for (int kt = 0; kt < 4; kt++) {
                const int base = (8 * j + g) * ASTR + 8 * kt + tq;
                uint32_t bhf[2], blf[2];
                bhf[0] = sK[0][base];     bhf[1] = sK[0][base + 4];
                blf[0] = sK[1][base];     blf[1] = sK[1][base + 4];
                MMA_BF16(s[j], qh[kt], bhf);
                MMA_BF16(s[j], ql[kt], bhf);
                MMA_BF16(s[j], qh[kt], blf);
            }
        }

        const bool diag = (jt == jq);
        #pragma unroll
        for (int j = 0; j < 8; j++) {
            #pragma unroll
            for (int c = 0; c < 4; c++) {
                s[j][c] *= INV_SCALE;
                if (diag) {
                    const int key = k0 + 8 * j + 2 * tq + (c & 1);
                    const int qg  = q0 + g + ((c >> 1) << 3);
                    if (key > qg) s[j][c] = -1e30f;
                }
            }
        }

        float mx0 = -1e30f, mx1 = -1e30f;
        #pragma unroll
        for (int j = 0; j < 8; j++) {
            mx0 = fmaxf(mx0, fmaxf(s[j][0], s[j][1]));
            mx1 = fmaxf(mx1, fmaxf(s[j][2], s[j][3]));
        }
        mx0 = fmaxf(mx0, __shfl_xor_sync(0xffffffffu, mx0, 1, 4));
        mx0 = fmaxf(mx0, __shfl_xor_sync(0xffffffffu, mx0, 2, 4));
        mx1 = fmaxf(mx1, __shfl_xor_sync(0xffffffffu, mx1, 1, 4));
        mx1 = fmaxf(mx1, __shfl_xor_sync(0xffffffffu, mx1, 2, 4));
        const float nm0 = fmaxf(mrow[0], mx0);
        const float nm1 = fmaxf(mrow[1], mx1);
        const float al0 = __expf(mrow[0] - nm0);
        const float al1 = __expf(mrow[1] - nm1);
        mrow[0] = nm0; mrow[1] = nm1;
        float rs0 = 0.0f, rs1 = 0.0f;
        #pragma unroll
        for (int j = 0; j < 8; j++) {
            s[j][0] = __expf(s[j][0] - nm0);
            s[j][1] = __expf(s[j][1] - nm0);
            s[j][2] = __expf(s[j][2] - nm1);
            s[j][3] = __expf(s[j][3] - nm1);
            rs0 += s[j][0] + s[j][1];
            rs1 += s[j][2] + s[j][3];
        }
        rs0 += __shfl_xor_sync(0xffffffffu, rs0, 1, 4);
        rs0 += __shfl_xor_sync(0xffffffffu, rs0, 2, 4);
        rs1 += __shfl_xor_sync(0xffffffffu, rs1, 1, 4);
        rs1 += __shfl_xor_sync(0xffffffffu, rs1, 2, 4);
        lrow[0] = lrow[0] * al0 + rs0;
        lrow[1] = lrow[1] * al1 + rs1;
        #pragma unroll
        for (int j = 0; j < 8; j++) {
            oacc[j][0] *= al0; oacc[j][1] *= al0;
            oacc[j][2] *= al1; oacc[j][3] *= al1;
        }

        uint32_t ph[4][4], pl[4][4];
        #pragma unroll
        for (int kt = 0; kt < 4; kt++) {
            const int j0 = 2 * kt, j1 = 2 * kt + 1;
            float v00 = s[j0][0], v01 = s[j0][1], v02 = s[j0][2], v03 = s[j0][3];
            float v10 = s[j1][0], v11 = s[j1][1], v12 = s[j1][2], v13 = s[j1][3];
            float h00 = __bfloat162float(__float2bfloat16_rn(v00));
            float h01 = __bfloat162float(__float2bfloat16_rn(v01));
            float h02 = __bfloat162float(__float2bfloat16_rn(v02));
            float h03 = __bfloat162float(__float2bfloat16_rn(v03));
            float h10 = __bfloat162float(__float2bfloat16_rn(v10));
            float h11 = __bfloat162float(__float2bfloat16_rn(v11));
            float h12 = __bfloat162float(__float2bfloat16_rn(v12));
            float h13 = __bfloat162float(__float2bfloat16_rn(v13));
            ph[kt][0] = pack_bf16x2(h00, h01);
            ph[kt][1] = pack_bf16x2(h02, h03);
            ph[kt][2] = pack_bf16x2(h10, h11);
            ph[kt][3] = pack_bf16x2(h12, h13);
            pl[kt][0] = pack_bf16x2(v00 - h00, v01 - h01);
            pl[kt][1] = pack_bf16x2(v02 - h02, v03 - h03);
            pl[kt][2] = pack_bf16x2(v10 - h10, v11 - h11);
            pl[kt][3] = pack_bf16x2(v12 - h12, v13 - h13);
        }

        #pragma unroll
        for (int j = 0; j < 8; j++) {
            #pragma unroll
            for (int kt = 0; kt < 4; kt++) {
                const int base = (8 * j + g) * ASTR + 8 * kt + tq;
                uint32_t vh[2], vl[2];
                vh[0] = sV[0][base];     vh[1] = sV[0][base + 4];
                vl[0] = sV[1][base];     vl[1] = sV[1][base + 4];
                MMA_BF16(oacc[j], ph[kt], vh);
                MMA_BF16(oacc[j], pl[kt], vh);
                MMA_BF16(oacc[j], ph[kt], vl);
            }
        }
    }

    const float il0 = 1.0f / lrow[0];
    const float il1 = 1.0f / lrow[1];
    #pragma unroll
    for (int j = 0; j < 8; j++) {
        const int col = h * HS + 8 * j + 2 * tq;
        const int qa = q0 + g;
        const int qb = q0 + g + 8;
        out[((size_t)(b * SS + qa)) * DD + col]     = oacc[j][0] * il0;
        out[((size_t)(b * SS + qa)) * DD + col + 1] = oacc[j][1] * il0;
        out[((size_t)(b * SS + qb)) * DD + col]     = oacc[j][2] * il1;
        out[((size_t)(b * SS + qb)) * DD + col + 1] = oacc[j][3] * il1;
    }
}

extern "C" void kernel_launch(void* const* d_in, const int* in_sizes, int n_in,
                              void* d_out, int out_size)
{
    const float* x  = (const float*)d_in[0];
    const float* Wq = (const float*)d_in[1];
    const float* bq = (const float*)d_in[2];
    const float* Wk = (const float*)d_in[3];
    const float* bk = (const float*)d_in[4];
    const float* Wv = (const float*)d_in[5];
    const float* bv = (const float*)d_in[6];
    float* out = (float*)d_out;

    prep_x_kernel<<<4096, 256>>>(x);                       // 4M elems / (256*4)
    prep_w_kernel<<<dim3(1024, 1, 3), 256>>>(Wq, Wk, Wv);  // 1M elems per z

    dim3 ggemm(DD / GBN, (BB * SS) / GBM, 3);  // 8 x 32 x 3
    qkv_gemm_kernel<<<ggemm, 256>>>(bq, bk, bv);

    dim3 gattn(SS / QT, BB * HH);              // 32 x 32
    attn_mma_kernel<<<gattn, 128>>>(out);
}

// round 9
// speedup vs baseline: 1.1679x; 1.1679x over previous
#include <cuda_runtime.h>
#include <cuda_bf16.h>
#include <cstdint>

// Problem constants
#define BB 2
#define SS 2048
#define DD 1024
#define HH 16
#define HS 64
#define INV_SCALE 0.125f

// Q,K: [bh][s][hs] bf16 hi/lo.  V: TRANSPOSED [bh][hs][s] bf16 hi/lo.
__device__ __nv_bfloat16 g_Qh[BB * HH * SS * HS];
__device__ __nv_bfloat16 g_Ql[BB * HH * SS * HS];
__device__ __nv_bfloat16 g_Kh[BB * HH * SS * HS];
__device__ __nv_bfloat16 g_Kl[BB * HH * SS * HS];
__device__ __nv_bfloat16 g_Vh[BB * HH * SS * HS];
__device__ __nv_bfloat16 g_Vl[BB * HH * SS * HS];

#define MMA_BF16(c, a, b) asm volatile( \
    "mma.sync.aligned.m16n8k16.row.col.f32.bf16.bf16.f32 " \
    "{%0,%1,%2,%3}, {%4,%5,%6,%7}, {%8,%9}, {%0,%1,%2,%3};\n" \
    : "+f"((c)[0]), "+f"((c)[1]), "+f"((c)[2]), "+f"((c)[3]) \
    : "r"((a)[0]), "r"((a)[1]), "r"((a)[2]), "r"((a)[3]), \
      "r"((b)[0]), "r"((b)[1]))

#define CP_ASYNC16(dst, src) asm volatile( \
    "cp.async.cg.shared.global [%0], [%1], 16;\n" :: "r"(dst), "l"(src))
#define CP_COMMIT() asm volatile("cp.async.commit_group;\n")
#define CP_WAIT1()  asm volatile("cp.async.wait_group 1;\n")
#define CP_WAIT0()  asm volatile("cp.async.wait_group 0;\n")

__device__ __forceinline__ uint32_t pack_bf16x2(float lo_elem, float hi_elem) {
    __nv_bfloat162 h = __floats2bfloat162_rn(lo_elem, hi_elem); // .x = low 16 bits
    uint32_t u;
    memcpy(&u, &h, 4);
    return u;
}

// ---------------------------------------------------------------------------
// QKV projection (bf16x3 compensated MMA) — R4 version, known 422us.
// Block 128x128, BK=32, 256 thr = 8 warps.
// ---------------------------------------------------------------------------
#define BM 128
#define BN 128
#define BK 32
#define STR32 20

__global__ __launch_bounds__(256) void qkv_mma_kernel(
    const float* __restrict__ x,
    const float* __restrict__ Wq, const float* __restrict__ bq,
    const float* __restrict__ Wk, const float* __restrict__ bk,
    const float* __restrict__ Wv, const float* __restrict__ bv)
{
    const float* __restrict__ W;
    const float* __restrict__ bias;
    __nv_bfloat16* __restrict__ outh;
    __nv_bfloat16* __restrict__ outl;
    bool vtrans = false;
    if (blockIdx.z == 0)      { W = Wq; bias = bq; outh = g_Qh; outl = g_Ql; }
    else if (blockIdx.z == 1) { W = Wk; bias = bk; outh = g_Kh; outl = g_Kl; }
    else                      { W = Wv; bias = bv; outh = g_Vh; outl = g_Vl; vtrans = true; }

    __shared__ uint32_t sA_hi[BM * STR32];
    __shared__ uint32_t sA_lo[BM * STR32];
    __shared__ uint32_t sB_hi[BN * STR32];
    __shared__ uint32_t sB_lo[BN * STR32];

    const int m0 = blockIdx.y * BM;
    const int n0 = blockIdx.x * BN;
    const int t    = threadIdx.x;
    const int wid  = t >> 5;
    const int lane = t & 31;
    const int wm = (wid & 1) * 64;
    const int wn = (wid >> 1) * 32;
    const int g  = lane >> 2;
    const int tq = lane & 3;

    const int lrow  = t >> 1;
    const int lhalf = (t & 1) * 16;
    const float* xptr = x + (long)(m0 + lrow) * DD + lhalf;
    const float* wptr = W + (long)(n0 + lrow) * DD + lhalf;
    const int sbase = lrow * STR32 + (lhalf >> 1);

    float acc[4][4][4];
    #pragma unroll
    for (int mi = 0; mi < 4; mi++)
        #pragma unroll
        for (int ni = 0; ni < 4; ni++)
            #pragma unroll
            for (int c = 0; c < 4; c++) acc[mi][ni][c] = 0.0f;

    float4 xa[4], wa[4];
    #pragma unroll
    for (int u = 0; u < 4; u++) {
        xa[u] = *(const float4*)(xptr + u * 4);
        wa[u] = *(const float4*)(wptr + u * 4);
    }

    for (int k0 = 0; k0 < DD; k0 += BK) {
        __syncthreads();
        #pragma unroll
        for (int u = 0; u < 4; u++) {
            float xs[4] = {xa[u].x, xa[u].y, xa[u].z, xa[u].w};
            float ws[4] = {wa[u].x, wa[u].y, wa[u].z, wa[u].w};
            #pragma unroll
            for (int p = 0; p < 2; p++) {
                float f0 = xs[2 * p], f1 = xs[2 * p + 1];
                float h0 = __bfloat162float(__float2bfloat16_rn(f0));
                float h1 = __bfloat162float(__float2bfloat16_rn(f1));
                sA_hi[sbase + u * 2 + p] = pack_bf16x2(h0, h1);
                sA_lo[sbase + u * 2 + p] = pack_bf16x2(f0 - h0, f1 - h1);
                float g0 = ws[2 * p], g1 = ws[2 * p + 1];
                float e0 = __bfloat162float(__float2bfloat16_rn(g0));
                float e1 = __bfloat162float(__float2bfloat16_rn(g1));
                sB_hi[sbase + u * 2 + p] = pack_bf16x2(e0, e1);
                sB_lo[sbase + u * 2 + p] = pack_bf16x2(g0 - e0, g1 - e1);
            }
        }
        __syncthreads();

        if (k0 + BK < DD) {
            #pragma unroll
            for (int u = 0; u < 4; u++) {
                xa[u] = *(const float4*)(xptr + k0 + BK + u * 4);
                wa[u] = *(const float4*)(wptr + k0 + BK + u * 4);
            }
        }

        #pragma unroll
        for (int kk = 0; kk < 2; kk++) {
            const int kc = kk * 8;
            uint32_t ah[4][4], al[4][4], bh[4][2], bl[4][2];
            #pragma unroll
            for (int mi = 0; mi < 4; mi++) {
                const int r = wm + mi * 16 + g;
                ah[mi][0] = sA_hi[r * STR32 + kc + tq];
                ah[mi][1] = sA_hi[(r + 8) * STR32 + kc + tq];
                ah[mi][2] = sA_hi[r * STR32 + kc + 4 + tq];
                ah[mi][3] = sA_hi[(r + 8) * STR32 + kc + 4 + tq];
                al[mi][0] = sA_lo[r * STR32 + kc + tq];
                al[mi][1] = sA_lo[(r + 8) * STR32 + kc + tq];
                al[mi][2] = sA_lo[r * STR32 + kc + 4 + tq];
                al[mi][3] = sA_lo[(r + 8) * STR32 + kc + 4 + tq];
            }
            #pragma unroll
            for (int ni = 0; ni < 4; ni++) {
                const int r = wn + ni * 8 + g;
                bh[ni][0] = sB_hi[r * STR32 + kc + tq];
                bh[ni][1] = sB_hi[r * STR32 + kc + 4 + tq];
                bl[ni][0] = sB_lo[r * STR32 + kc + tq];
                bl[ni][1] = sB_lo[r * STR32 + kc + 4 + tq];
            }
            #pragma unroll
            for (int mi = 0; mi < 4; mi++) {
                #pragma unroll
                for (int ni = 0; ni < 4; ni++) {
                    MMA_BF16(acc[mi][ni], ah[mi], bh[ni]);
                    MMA_BF16(acc[mi][ni], ah[mi], bl[ni]);
                    MMA_BF16(acc[mi][ni], al[mi], bh[ni]);
                }
            }
        }
    }

    #pragma unroll
    for (int mi = 0; mi < 4; mi++) {
        #pragma unroll
        for (int ni = 0; ni < 4; ni++) {
            const int r0 = m0 + wm + mi * 16 + g;
            const int c0 = n0 + wn + ni * 8 + 2 * tq;
            #pragma unroll
            for (int c = 0; c < 4; c++) {
                const int row = r0 + (c >> 1) * 8;
                const int col = c0 + (c & 1);
                const int b_  = row >> 11;
                const int s_  = row & (SS - 1);
                const int h_  = col >> 6;
                const int hs_ = col & (HS - 1);
                const float v = acc[mi][ni][c] + __ldg(&bias[col]);
                __nv_bfloat16 vh = __float2bfloat16_rn(v);
                __nv_bfloat16 vl = __float2bfloat16_rn(v - __bfloat162float(vh));
                size_t idx;
                if (!vtrans) idx = ((size_t)(b_ * HH + h_) * SS + s_) * HS + hs_;
                else         idx = ((size_t)(b_ * HH + h_) * HS + hs_) * SS + s_;
                outh[idx] = vh;
                outl[idx] = vl;
            }
        }
    }
}

// ---------------------------------------------------------------------------
// Flash attention, bf16x3 MMA, causal.
// QT=128 (8 warps x 16 q-rows, 256 thr), KT=64, cp.async double-buffered
// K/V tiles in dynamic smem (2 x 36KB). Per-warp skip of fully-masked tiles.
// ---------------------------------------------------------------------------
#define QT2 128
#define KT 64
#define ASTR 36
#define ARR 2304            // u32 per array (64*36)
#define BUFW (4 * ARR)      // words per buffer: Kh,Kl,Vh,Vl
#define ATTN_SMEM (2 * BUFW * 4)   // 73728 bytes

extern __shared__ uint32_t dsm[];

__global__ __launch_bounds__(256) void attn_mma_kernel(float* __restrict__ out)
{
    const int bh = blockIdx.y;
    const int jq = (SS / QT2 - 1) - blockIdx.x;   // heavy tiles first
    const int b  = bh >> 4;
    const int h  = bh & (HH - 1);

    const int t    = threadIdx.x;
    const int wid  = t >> 5;
    const int lane = t & 31;
    const int g  = lane >> 2;
    const int tq = lane & 3;
    const int q0 = jq * QT2 + wid * 16;

    const uint32_t* Qh32 = (const uint32_t*)g_Qh + (size_t)bh * SS * (HS / 2);
    const uint32_t* Ql32 = (const uint32_t*)g_Ql + (size_t)bh * SS * (HS / 2);
    const uint32_t* Kh32 = (const uint32_t*)g_Kh + (size_t)bh * SS * (HS / 2);
    const uint32_t* Kl32 = (const uint32_t*)g_Kl + (size_t)bh * SS * (HS / 2);
    const uint32_t* Vh32 = (const uint32_t*)g_Vh + (size_t)bh * HS * (SS / 2);
    const uint32_t* Vl32 = (const uint32_t*)g_Vl + (size_t)bh * HS * (SS / 2);

    // Q fragments, register-resident for whole block
    uint32_t qh[4][4], ql[4][4];
    #pragma unroll
    for (int kt = 0; kt < 4; kt++) {
        const int w = 8 * kt + tq;
        qh[kt][0] = Qh32[(size_t)(q0 + g) * 32 + w];
        qh[kt][1] = Qh32[(size_t)(q0 + g + 8) * 32 + w];
        qh[kt][2] = Qh32[(size_t)(q0 + g) * 32 + w + 4];
        qh[kt][3] = Qh32[(size_t)(q0 + g + 8) * 32 + w + 4];
        ql[kt][0] = Ql32[(size_t)(q0 + g) * 32 + w];
        ql[kt][1] = Ql32[(size_t)(q0 + g + 8) * 32 + w];
        ql[kt][2] = Ql32[(size_t)(q0 + g) * 32 + w + 4];
        ql[kt][3] = Ql32[(size_t)(q0 + g + 8) * 32 + w + 4];
    }

    float oacc[8][4];
    #pragma unroll
    for (int j = 0; j < 8; j++)
        #pragma unroll
        for (int c = 0; c < 4; c++) oacc[j][c] = 0.0f;
    float mrow[2] = {-1e30f, -1e30f};
    float lrow[2] = {0.0f, 0.0f};

    // cp.async copy mapping: thread -> (array, row). arrays: 0=Kh 1=Kl 2=Vh 3=Vl
    const int ca = t >> 6;
    const int cr = t & 63;
    const uint32_t sbase = (uint32_t)__cvta_generic_to_shared(dsm);

    const int jtmax = 2 * jq + 1;

    // prologue: copy tile 0 into buffer 0
    {
        const uint32_t* src =
            (ca == 0) ? Kh32 + (size_t)cr * 32 :
            (ca == 1) ? Kl32 + (size_t)cr * 32 :
            (ca == 2) ? Vh32 + (size_t)cr * (SS / 2) :
                        Vl32 + (size_t)cr * (SS / 2);
        const uint32_t dst = sbase + (uint32_t)((ca * ARR + cr * ASTR) * 4);
        #pragma unroll
        for (int c = 0; c < 8; c++) CP_ASYNC16(dst + c * 16, src + c * 4);
        CP_COMMIT();
    }

    for (int jt = 0; jt <= jtmax; jt++) {
        const int k0  = jt * KT;
        const int buf = jt & 1;

        if (jt < jtmax) {
            const int kn = k0 + KT;
            const uint32_t* src =
                (ca == 0) ? Kh32 + (size_t)(kn + cr) * 32 :
                (ca == 1) ? Kl32 + (size_t)(kn + cr) * 32 :
                (ca == 2) ? Vh32 + (size_t)cr * (SS / 2) + (kn >> 1) :
                            Vl32 + (size_t)cr * (SS / 2) + (kn >> 1);
            const uint32_t dst = sbase +
                (uint32_t)(((buf ^ 1) * BUFW + ca * ARR + cr * ASTR) * 4);
            #pragma unroll
            for (int c = 0; c < 8; c++) CP_ASYNC16(dst + c * 16, src + c * 4);
            CP_COMMIT();
            CP_WAIT1();
        } else {
            CP_WAIT0();
        }
        __syncthreads();

        if (k0 <= q0 + 15) {   // tile not fully masked for this warp
            const uint32_t* bKh = dsm + buf * BUFW;
            const uint32_t* bKl = bKh + ARR;
            const uint32_t* bVh = bKh + 2 * ARR;
            const uint32_t* bVl = bKh + 3 * ARR;

            // S = Q K^T (bf16x3)
            float s[8][4];
            #pragma unroll
            for (int j = 0; j < 8; j++)
                #pragma unroll
                for (int c = 0; c < 4; c++) s[j][c] = 0.0f;
            #pragma unroll
            for (int j = 0; j < 8; j++) {
                #pragma unroll
                for (int kt = 0; kt < 4; kt++) {
                    const int base = (8 * j + g) * ASTR + 8 * kt + tq;
                    uint32_t bhf[2], blf[2];
                    bhf[0] = bKh[base];     bhf[1] = bKh[base + 4];
                    blf[0] = bKl[base];     blf[1] = bKl[base + 4];
                    MMA_BF16(s[j], qh[kt], bhf);
                    MMA_BF16(s[j], ql[kt], bhf);
                    MMA_BF16(s[j], qh[kt], blf);
                }
            }

            // scale + causal mask (tiles overlapping this warp's rows)
            const bool diag = (k0 + KT - 1 > q0);
            #pragma unroll
            for (int j = 0; j < 8; j++) {
                #pragma unroll
                for (int c = 0; c < 4; c++) {
                    s[j][c] *= INV_SCALE;
                    if (diag) {
                        const int key = k0 + 8 * j + 2 * tq + (c & 1);
                        const int qg  = q0 + g + ((c >> 1) << 3);
                        if (key > qg) s[j][c] = -1e30f;
                    }
                }
            }

            // online softmax (rows g and g+8; reduce over 4 tq lanes)
            float mx0 = -1e30f, mx1 = -1e30f;
            #pragma unroll
            for (int j = 0; j < 8; j++) {
                mx0 = fmaxf(mx0, fmaxf(s[j][0], s[j][1]));
                mx1 = fmaxf(mx1, fmaxf(s[j][2], s[j][3]));
            }
            mx0 = fmaxf(mx0, __shfl_xor_sync(0xffffffffu, mx0, 1, 4));
            mx0 = fmaxf(mx0, __shfl_xor_sync(0xffffffffu, mx0, 2, 4));
            mx1 = fmaxf(mx1, __shfl_xor_sync(0xffffffffu, mx1, 1, 4));
            mx1 = fmaxf(mx1, __shfl_xor_sync(0xffffffffu, mx1, 2, 4));
            const float nm0 = fmaxf(mrow[0], mx0);
            const float nm1 = fmaxf(mrow[1], mx1);
            const float al0 = __expf(mrow[0] - nm0);
            const float al1 = __expf(mrow[1] - nm1);
            mrow[0] = nm0; mrow[1] = nm1;
            float rs0 = 0.0f, rs1 = 0.0f;
            #pragma unroll
            for (int j = 0; j < 8; j++) {
                s[j][0] = __expf(s[j][0] - nm0);
                s[j][1] = __expf(s[j][1] - nm0);
                s[j][2] = __expf(s[j][2] - nm1);
                s[j][3] = __expf(s[j][3] - nm1);
                rs0 += s[j][0] + s[j][1];
                rs1 += s[j][2] + s[j][3];
            }
            rs0 += __shfl_xor_sync(0xffffffffu, rs0, 1, 4);
            rs0 += __shfl_xor_sync(0xffffffffu, rs0, 2, 4);
            rs1 += __shfl_xor_sync(0xffffffffu, rs1, 1, 4);
            rs1 += __shfl_xor_sync(0xffffffffu, rs1, 2, 4);
            lrow[0] = lrow[0] * al0 + rs0;
            lrow[1] = lrow[1] * al1 + rs1;
            #pragma unroll
            for (int j = 0; j < 8; j++) {
                oacc[j][0] *= al0; oacc[j][1] *= al0;
                oacc[j][2] *= al1; oacc[j][3] *= al1;
            }

            // P: S C-frag -> A-frag, hi/lo split in registers
            uint32_t ph[4][4], pl[4][4];
            #pragma unroll
            for (int kt = 0; kt < 4; kt++) {
                const int j0 = 2 * kt, j1 = 2 * kt + 1;
                float v00 = s[j0][0], v01 = s[j0][1], v02 = s[j0][2], v03 = s[j0][3];
                float v10 = s[j1][0], v11 = s[j1][1], v12 = s[j1][2], v13 = s[j1][3];
                float h00 = __bfloat162float(__float2bfloat16_rn(v00));
                float h01 = __bfloat162float(__float2bfloat16_rn(v01));
                float h02 = __bfloat162float(__float2bfloat16_rn(v02));
                float h03 = __bfloat162float(__float2bfloat16_rn(v03));
                float h10 = __bfloat162float(__float2bfloat16_rn(v10));
                float h11 = __bfloat162float(__float2bfloat16_rn(v11));
                float h12 = __bfloat162float(__float2bfloat16_rn(v12));
                float h13 = __bfloat162float(__float2bfloat16_rn(v13));
                ph[kt][0] = pack_bf16x2(h00, h01);
                ph[kt][1] = pack_bf16x2(h02, h03);
                ph[kt][2] = pack_bf16x2(h10, h11);
                ph[kt][3] = pack_bf16x2(h12, h13);
                pl[kt][0] = pack_bf16x2(v00 - h00, v01 - h01);
                pl[kt][1] = pack_bf16x2(v02 - h02, v03 - h03);
                pl[kt][2] = pack_bf16x2(v10 - h10, v11 - h11);
                pl[kt][3] = pack_bf16x2(v12 - h12, v13 - h13);
            }

            // O += P V (bf16x3); V^T in smem, j indexes d-tiles
            #pragma unroll
            for (int j = 0; j < 8; j++) {
                #pragma unroll
                for (int kt = 0; kt < 4; kt++) {
                    const int base = (8 * j + g) * ASTR + 8 * kt + tq;
                    uint32_t vh[2], vl[2];
                    vh[0] = bVh[base];     vh[1] = bVh[base + 4];
                    vl[0] = bVl[base];     vl[1] = bVl[base + 4];
                    MMA_BF16(oacc[j], ph[kt], vh);
                    MMA_BF16(oacc[j], pl[kt], vh);
                    MMA_BF16(oacc[j], ph[kt], vl);
                }
            }
        }
        __syncthreads();   // all warps done reading buf before it is refilled
    }

    // Epilogue: normalize, write out[b, q, h*64 + d]
    const float il0 = 1.0f / lrow[0];
    const float il1 = 1.0f / lrow[1];
    #pragma unroll
    for (int j = 0; j < 8; j++) {
        const int col = h * HS + 8 * j + 2 * tq;
        const int qa = q0 + g;
        const int qb = q0 + g + 8;
        out[((size_t)(b * SS + qa)) * DD + col]     = oacc[j][0] * il0;
        out[((size_t)(b * SS + qa)) * DD + col + 1] = oacc[j][1] * il0;
        out[((size_t)(b * SS + qb)) * DD + col]     = oacc[j][2] * il1;
        out[((size_t)(b * SS + qb)) * DD + col + 1] = oacc[j][3] * il1;
    }
}

extern "C" void kernel_launch(void* const* d_in, const int* in_sizes, int n_in,
                              void* d_out, int out_size)
{
    const float* x  = (const float*)d_in[0];
    const float* Wq = (const float*)d_in[1];
    const float* bq = (const float*)d_in[2];
    const float* Wk = (const float*)d_in[3];
    const float* bk = (const float*)d_in[4];
    const float* Wv = (const float*)d_in[5];
    const float* bv = (const float*)d_in[6];
    float* out = (float*)d_out;

    static bool attr_set = false;
    if (!attr_set) {
        cudaFuncSetAttribute(attn_mma_kernel,
                             cudaFuncAttributeMaxDynamicSharedMemorySize,
                             ATTN_SMEM);
        attr_set = true;
    }

    dim3 gproj(DD / BN, (BB * SS) / BM, 3);   // 8 x 32 x 3
    qkv_mma_kernel<<<gproj, 256>>>(x, Wq, bq, Wk, bk, Wv, bv);

    dim3 gattn(SS / QT2, BB * HH);            // 16 x 32
    attn_mma_kernel<<<gattn, 256, ATTN_SMEM>>>(out);
}